// round 15
// baseline (speedup 1.0000x reference)
#include <cuda_runtime.h>
#include <cuda_bf16.h>
#include <cstdint>

#define NN 100000
#define NE 1600000
#define FF 128
#define CC 64
#define SCAN_B 1024
#define SCAN_NB ((NN + SCAN_B - 1) / SCAN_B)   // 98

// ======================= scratch (static device globals) =======================
__device__ int   g_cnt[NN];
__device__ int   g_rowptr[NN + 1];
__device__ int   g_cursor[NN];
__device__ int   g_tilesum[SCAN_NB];
__device__ int   g_bar1 = 0, g_bar2 = 0;       // grid barriers (reset by k_fill)
__device__ int   g_col[NE];
__device__ uint32_t g_xbf[(size_t)NN * 64];    // x packed bf16x2 (written by k_gemm0)
__device__ uint32_t g_m[(size_t)NN * 64];      // mean(x) packed bf16x2
__device__ uint32_t g_xrbf[(size_t)NN * 64];   // xr = x @ W1r^T packed bf16x2
__device__ uint32_t g_pbf[(size_t)NN * 32];    // P = h@W2l^T packed bf16x2
__device__ float g_q[(size_t)NN * 64];         // Q = h@W2r^T + b2l (fp32)
// weights as plain bf16, row-major [n][k]
__device__ unsigned short g_w1[128 * 256];     // [W1l | W1r]
__device__ unsigned short g_w2[128 * 128];     // [W2l ; W2r]

// ======================= small helpers =======================
__device__ __forceinline__ uint32_t smem_to_u32(const void* p) {
    uint32_t a;
    asm("{ .reg .u64 t; cvta.to.shared.u64 t, %1; cvt.u32.u64 %0, t; }" : "=r"(a) : "l"(p));
    return a;
}

__device__ __forceinline__ void ldm_x4(uint32_t* r, uint32_t addr) {
    asm volatile("ldmatrix.sync.aligned.m8n8.x4.shared.b16 {%0,%1,%2,%3}, [%4];"
                 : "=r"(r[0]), "=r"(r[1]), "=r"(r[2]), "=r"(r[3]) : "r"(addr));
}

__device__ __forceinline__ void mma_bf16(float* d, const uint32_t* a, uint32_t b0, uint32_t b1) {
    asm volatile(
        "mma.sync.aligned.m16n8k16.row.col.f32.bf16.bf16.f32 "
        "{%0,%1,%2,%3}, {%4,%5,%6,%7}, {%8,%9}, {%0,%1,%2,%3};"
        : "+f"(d[0]), "+f"(d[1]), "+f"(d[2]), "+f"(d[3])
        : "r"(a[0]), "r"(a[1]), "r"(a[2]), "r"(a[3]), "r"(b0), "r"(b1));
}

__device__ __forceinline__ uint32_t pack_bf16x2(float a, float b) {
    return (uint32_t)__bfloat16_as_ushort(__float2bfloat16(a))
         | ((uint32_t)__bfloat16_as_ushort(__float2bfloat16(b)) << 16);
}

__device__ __forceinline__ float bf_lo(uint32_t w) { return __uint_as_float(w << 16); }
__device__ __forceinline__ float bf_hi(uint32_t w) { return __uint_as_float(w & 0xffff0000u); }

// ======================= fused count + scan (one kernel, grid barriers) ==========
// 98 blocks x 1024 threads; all co-resident (98 <= 148 SMs) => barrier is safe.
__global__ void __launch_bounds__(SCAN_B)
k_countscan(const int* __restrict__ dst) {
    __shared__ int warp_sums[32];
    __shared__ int s_base;
    const int t = threadIdx.x, lane = t & 31, wid = t >> 5;
    const int tile = blockIdx.x;
    const int gid = tile * SCAN_B + t;

    // ---- phase A: count (16 edges per thread; NE/16 = 100000 exactly) ----
    {
        int e0 = gid * 16;
        if (e0 < NE) {
#pragma unroll
            for (int j = 0; j < 4; j++) {
                int4 d = *(const int4*)(dst + e0 + j * 4);
                atomicAdd(&g_cnt[d.x], 1);
                atomicAdd(&g_cnt[d.y], 1);
                atomicAdd(&g_cnt[d.z], 1);
                atomicAdd(&g_cnt[d.w], 1);
            }
        }
    }
    __threadfence();
    __syncthreads();
    if (t == 0) {
        atomicAdd(&g_bar1, 1);
        while (atomicAdd(&g_bar1, 0) < SCAN_NB) {}
    }
    __syncthreads();

    // ---- phase B: block-local scan of this block's tile ----
    const int i = tile * SCAN_B + t;
    int v = 0;
    if (i < NN) {
        v = __ldcg(&g_cnt[i]);     // atomics wrote L2; bypass L1
        g_cnt[i] = 0;              // re-zero for next replay
    }
    int s = v;
#pragma unroll
    for (int o = 1; o < 32; o <<= 1) {
        int u = __shfl_up_sync(0xffffffffu, s, o);
        if (lane >= o) s += u;
    }
    if (lane == 31) warp_sums[wid] = s;
    __syncthreads();
    if (wid == 0) {
        int ws = warp_sums[lane];
#pragma unroll
        for (int o = 1; o < 32; o <<= 1) {
            int u = __shfl_up_sync(0xffffffffu, ws, o);
            if (lane >= o) ws += u;
        }
        warp_sums[lane] = ws;
    }
    __syncthreads();
    const int incl  = s + (wid ? warp_sums[wid - 1] : 0);
    const int total = warp_sums[31];

    // publish tile total, grid barrier 2
    if (t == 0) {
        g_tilesum[tile] = total;
        __threadfence();
        atomicAdd(&g_bar2, 1);
        while (atomicAdd(&g_bar2, 0) < SCAN_NB) {}
    }
    __syncthreads();

    // warp 0 computes exclusive base over tile sums
    if (wid == 0) {
        int acc = 0;
#pragma unroll
        for (int r = 0; r < 4; r++) {
            int j = r * 32 + lane;
            if (j < tile && j < SCAN_NB) acc += __ldcg(&g_tilesum[j]);
        }
#pragma unroll
        for (int o = 16; o; o >>= 1) acc += __shfl_xor_sync(0xffffffffu, acc, o);
        if (lane == 0) s_base = acc;
    }
    __syncthreads();

    if (i < NN) {
        int r = s_base + incl - v;
        g_rowptr[i] = r;
        g_cursor[i] = r;
    }
    if (i == 0) g_rowptr[NN] = NE;
}

// fill: 4 edges per thread; also resets the grid-barrier counters for next replay
__global__ void k_fill(const int* __restrict__ src, const int* __restrict__ dst) {
    int gt = blockIdx.x * blockDim.x + threadIdx.x;
    if (gt == 0) { g_bar1 = 0; g_bar2 = 0; }
    int e = gt * 4;
    if (e < NE) {
        int4 d = *(const int4*)(dst + e);
        int4 s = *(const int4*)(src + e);
        int p0 = atomicAdd(&g_cursor[d.x], 1);
        int p1 = atomicAdd(&g_cursor[d.y], 1);
        int p2 = atomicAdd(&g_cursor[d.z], 1);
        int p3 = atomicAdd(&g_cursor[d.w], 1);
        g_col[p0] = s.x;
        g_col[p1] = s.y;
        g_col[p2] = s.z;
        g_col[p3] = s.w;
    }
}

// ======================= aggregation (warp per node, bf16 gather, unroll 8) =======
__global__ void k_agg128() {
    int node = blockIdx.x * (blockDim.x >> 5) + (threadIdx.x >> 5);
    if (node >= NN) return;
    int lane = threadIdx.x & 31;
    int b = g_rowptr[node], e = g_rowptr[node + 1];
    float a0 = 0.f, a1 = 0.f, a2 = 0.f, a3 = 0.f;
    int i = b;
    for (; i + 8 <= e; i += 8) {
        int u0 = g_col[i + 0], u1 = g_col[i + 1], u2 = g_col[i + 2], u3 = g_col[i + 3];
        int u4 = g_col[i + 4], u5 = g_col[i + 5], u6 = g_col[i + 6], u7 = g_col[i + 7];
        uint2 w0 = *((const uint2*)(g_xbf + (size_t)u0 * 64) + lane);
        uint2 w1 = *((const uint2*)(g_xbf + (size_t)u1 * 64) + lane);
        uint2 w2 = *((const uint2*)(g_xbf + (size_t)u2 * 64) + lane);
        uint2 w3 = *((const uint2*)(g_xbf + (size_t)u3 * 64) + lane);
        uint2 w4 = *((const uint2*)(g_xbf + (size_t)u4 * 64) + lane);
        uint2 w5 = *((const uint2*)(g_xbf + (size_t)u5 * 64) + lane);
        uint2 w6 = *((const uint2*)(g_xbf + (size_t)u6 * 64) + lane);
        uint2 w7 = *((const uint2*)(g_xbf + (size_t)u7 * 64) + lane);
        a0 += ((bf_lo(w0.x) + bf_lo(w1.x)) + (bf_lo(w2.x) + bf_lo(w3.x)))
            + ((bf_lo(w4.x) + bf_lo(w5.x)) + (bf_lo(w6.x) + bf_lo(w7.x)));
        a1 += ((bf_hi(w0.x) + bf_hi(w1.x)) + (bf_hi(w2.x) + bf_hi(w3.x)))
            + ((bf_hi(w4.x) + bf_hi(w5.x)) + (bf_hi(w6.x) + bf_hi(w7.x)));
        a2 += ((bf_lo(w0.y) + bf_lo(w1.y)) + (bf_lo(w2.y) + bf_lo(w3.y)))
            + ((bf_lo(w4.y) + bf_lo(w5.y)) + (bf_lo(w6.y) + bf_lo(w7.y)));
        a3 += ((bf_hi(w0.y) + bf_hi(w1.y)) + (bf_hi(w2.y) + bf_hi(w3.y)))
            + ((bf_hi(w4.y) + bf_hi(w5.y)) + (bf_hi(w6.y) + bf_hi(w7.y)));
    }
    for (; i < e; i++) {
        uint2 w = *((const uint2*)(g_xbf + (size_t)g_col[i] * 64) + lane);
        a0 += bf_lo(w.x); a1 += bf_hi(w.x);
        a2 += bf_lo(w.y); a3 += bf_hi(w.y);
    }
    float inv = 1.f / (float)max(e - b, 1);
    *((uint2*)(g_m + (size_t)node * 64) + lane) =
        make_uint2(pack_bf16x2(a0 * inv, a1 * inv), pack_bf16x2(a2 * inv, a3 * inv));
}

// ======================= weight prep (plain bf16) =======================
__global__ void k_prepW(const float* __restrict__ W1l, const float* __restrict__ W1r,
                        const float* __restrict__ W2l, const float* __restrict__ W2r) {
    int idx = blockIdx.x * blockDim.x + threadIdx.x;
    if (idx < 128 * 256) {
        int n = idx >> 8, k = idx & 255;
        float w = (k < 128) ? W1l[n * 128 + k] : W1r[n * 128 + (k - 128)];
        g_w1[idx] = __bfloat16_as_ushort(__float2bfloat16(w));
    } else {
        int i2 = idx - 128 * 256;
        if (i2 < 128 * 128) {
            int n = i2 >> 7, k = i2 & 127;
            float w = (n < 64) ? W2l[n * 128 + k] : W2r[(n - 64) * 128 + k];
            g_w2[i2] = __bfloat16_as_ushort(__float2bfloat16(w));
        }
    }
}

// ======================= single-term bf16 HMMA GEMMs =======================
#define BSTR 136   // bf16 per smem row (272B: conflict-free ldmatrix/frag access)

// GEMM 0 (side stream): xr = x @ W1r^T  -> g_xrbf ; ALSO emits g_xbf = bf16(x)
__global__ void __launch_bounds__(256, 2)
k_gemm0(const float* __restrict__ X)
{
    constexpr int AOFF = 0;
    constexpr int BOFF = 128 * BSTR * 2;   // 34816
    extern __shared__ char smem[];
    const uint32_t smem_base = smem_to_u32(smem);
    const int tid = threadIdx.x, warp = tid >> 5, lane = tid & 31;
    const int wr = warp >> 2, wc = warp & 3;
    const int mbase = blockIdx.x * 128;

    for (int i = tid; i < 128 * 16; i += 256) {
        int n = i >> 4, c = i & 15;
        *(uint4*)(smem + BOFF + n * (BSTR * 2) + c * 16) = ((const uint4*)g_w1)[n * 32 + 16 + c];
    }
    // A-load: read x fp32, convert once, feed smem AND g_xbf
    {
        int row = tid >> 1, half = tid & 1;
        int gr = mbase + row;
        bool valid = gr < NN;
        const float4* srcf = (const float4*)(X + (size_t)gr * 128 + half * 64);
        uint32_t* dA = (uint32_t*)(smem + AOFF + row * (BSTR * 2) + half * 128);
        uint32_t* dG = g_xbf + (size_t)gr * 64 + half * 32;
        uint32_t pk[32];
#pragma unroll
        for (int j = 0; j < 16; j++) {
            float4 v = make_float4(0.f, 0.f, 0.f, 0.f);
            if (valid) v = srcf[j];
            pk[2 * j]     = pack_bf16x2(v.x, v.y);
            pk[2 * j + 1] = pack_bf16x2(v.z, v.w);
        }
#pragma unroll
        for (int j = 0; j < 8; j++)
            *(uint4*)(dA + j * 4) = make_uint4(pk[4 * j], pk[4 * j + 1], pk[4 * j + 2], pk[4 * j + 3]);
        if (valid) {
#pragma unroll
            for (int j = 0; j < 8; j++)
                *(uint4*)(dG + j * 4) = make_uint4(pk[4 * j], pk[4 * j + 1], pk[4 * j + 2], pk[4 * j + 3]);
        }
    }
    __syncthreads();

    float acc[4][4][4];
#pragma unroll
    for (int mt = 0; mt < 4; mt++)
#pragma unroll
        for (int nt = 0; nt < 4; nt++)
#pragma unroll
            for (int q = 0; q < 4; q++) acc[mt][nt][q] = 0.f;

    const uint32_t a_off = (uint32_t)(((lane & 15) * BSTR + (lane >> 4) * 8) * 2);
    const uint32_t* Bp = (const uint32_t*)(smem + BOFF);

#pragma unroll
    for (int ks = 0; ks < 8; ks++) {
        const int k0 = ks * 16;
        uint32_t bf[4][2];
#pragma unroll
        for (int nt = 0; nt < 4; nt++) {
            int n = wc * 32 + nt * 8 + (lane >> 2);
            int bi = n * (BSTR / 2) + k0 / 2 + (lane & 3);
            bf[nt][0] = Bp[bi]; bf[nt][1] = Bp[bi + 4];
        }
#pragma unroll
        for (int mt = 0; mt < 4; mt++) {
            uint32_t ahp = smem_base + AOFF + (uint32_t)((wr * 64 + mt * 16) * BSTR + k0) * 2 + a_off;
            uint32_t ah[4];
            ldm_x4(ah, ahp);
#pragma unroll
            for (int nt = 0; nt < 4; nt++)
                mma_bf16(acc[mt][nt], ah, bf[nt][0], bf[nt][1]);
        }
    }

#pragma unroll
    for (int nt = 0; nt < 4; nt++) {
        int col = wc * 32 + nt * 8 + (lane & 3) * 2;
#pragma unroll
        for (int mt = 0; mt < 4; mt++) {
            int row0 = mbase + wr * 64 + mt * 16 + (lane >> 2);
#pragma unroll
            for (int hrow = 0; hrow < 2; hrow++) {
                int row = row0 + hrow * 8;
                if (row < NN)
                    g_xrbf[(size_t)row * 64 + (col >> 1)] =
                        pack_bf16x2(acc[mt][nt][hrow * 2], acc[mt][nt][hrow * 2 + 1]);
            }
        }
    }
}

// fused GEMM 1+2 (A = g_m from global)
__global__ void __launch_bounds__(256, 2)
k_gemm12(const float* __restrict__ b1, const float* __restrict__ b2)
{
    constexpr int AOFF = 0;
    constexpr int BOFF = 128 * BSTR * 2;       // 34816
    constexpr int HOFF = 2 * 128 * BSTR * 2;   // 69632 ; total 104448
    extern __shared__ char smem[];
    const uint32_t smem_base = smem_to_u32(smem);
    const int tid = threadIdx.x, warp = tid >> 5, lane = tid & 31;
    const int wr = warp >> 2, wc = warp & 3;
    const int mbase = blockIdx.x * 128;

    for (int i = tid; i < 128 * 16; i += 256) {
        int n = i >> 4, c = i & 15;
        *(uint4*)(smem + BOFF + n * (BSTR * 2) + c * 16) = ((const uint4*)g_w1)[n * 32 + c];
    }
    {
        int row = tid >> 1, half = tid & 1;
        int gr = mbase + row;
        bool valid = gr < NN;
        const uint4* src = (const uint4*)(g_m + (size_t)gr * 64 + half * 32);
        char* dA = smem + AOFF + row * (BSTR * 2) + half * 128;
#pragma unroll
        for (int j = 0; j < 8; j++) {
            uint4 v = make_uint4(0u, 0u, 0u, 0u);
            if (valid) v = src[j];
            *(uint4*)(dA + j * 16) = v;
        }
    }
    __syncthreads();

    float acc[4][4][4];
#pragma unroll
    for (int mt = 0; mt < 4; mt++)
#pragma unroll
        for (int nt = 0; nt < 4; nt++)
#pragma unroll
            for (int q = 0; q < 4; q++) acc[mt][nt][q] = 0.f;

    const uint32_t a_off = (uint32_t)(((lane & 15) * BSTR + (lane >> 4) * 8) * 2);
    const uint32_t* Bp = (const uint32_t*)(smem + BOFF);

    // ---- mainloop 1 ----
#pragma unroll
    for (int ks = 0; ks < 8; ks++) {
        const int k0 = ks * 16;
        uint32_t bf[4][2];
#pragma unroll
        for (int nt = 0; nt < 4; nt++) {
            int n = wc * 32 + nt * 8 + (lane >> 2);
            int bi = n * (BSTR / 2) + k0 / 2 + (lane & 3);
            bf[nt][0] = Bp[bi]; bf[nt][1] = Bp[bi + 4];
        }
#pragma unroll
        for (int mt = 0; mt < 4; mt++) {
            uint32_t ahp = smem_base + AOFF + (uint32_t)((wr * 64 + mt * 16) * BSTR + k0) * 2 + a_off;
            uint32_t ah[4];
            ldm_x4(ah, ahp);
#pragma unroll
            for (int nt = 0; nt < 4; nt++)
                mma_bf16(acc[mt][nt], ah, bf[nt][0], bf[nt][1]);
        }
    }

    // ---- epilogue 1: h -> smem H (bf16) ----
#pragma unroll
    for (int nt = 0; nt < 4; nt++) {
        int col = wc * 32 + nt * 8 + (lane & 3) * 2;
        float bias0 = __ldg(b1 + col);
        float bias1 = __ldg(b1 + col + 1);
#pragma unroll
        for (int mt = 0; mt < 4; mt++) {
            int rl0 = wr * 64 + mt * 16 + (lane >> 2);
#pragma unroll
            for (int hrow = 0; hrow < 2; hrow++) {
                int rl = rl0 + hrow * 8;
                int grow = mbase + rl;
                float xr0 = 0.f, xr1 = 0.f;
                if (grow < NN) {
                    uint32_t w = g_xrbf[(size_t)grow * 64 + (col >> 1)];
                    xr0 = bf_lo(w); xr1 = bf_hi(w);
                }
                float v0 = fmaxf(acc[mt][nt][hrow * 2]     + xr0 + bias0, 0.f);
                float v1 = fmaxf(acc[mt][nt][hrow * 2 + 1] + xr1 + bias1, 0.f);
                *(uint32_t*)(smem + HOFF + rl * (BSTR * 2) + (col >> 1) * 4) = pack_bf16x2(v0, v1);
            }
        }
    }
    __syncthreads();

    // ---- W2 into B region ----
    for (int i = tid; i < 128 * 16; i += 256) {
        int n = i >> 4, c = i & 15;
        *(uint4*)(smem + BOFF + n * (BSTR * 2) + c * 16) = ((const uint4*)g_w2)[n * 16 + c];
    }
#pragma unroll
    for (int mt = 0; mt < 4; mt++)
#pragma unroll
        for (int nt = 0; nt < 4; nt++)
#pragma unroll
            for (int q = 0; q < 4; q++) acc[mt][nt][q] = 0.f;
    __syncthreads();

    // ---- mainloop 2: A = H ----
#pragma unroll
    for (int ks = 0; ks < 8; ks++) {
        const int k0 = ks * 16;
        uint32_t bf[4][2];
#pragma unroll
        for (int nt = 0; nt < 4; nt++) {
            int n = wc * 32 + nt * 8 + (lane >> 2);
            int bi = n * (BSTR / 2) + k0 / 2 + (lane & 3);
            bf[nt][0] = Bp[bi]; bf[nt][1] = Bp[bi + 4];
        }
#pragma unroll
        for (int mt = 0; mt < 4; mt++) {
            uint32_t ahp = smem_base + HOFF + (uint32_t)((wr * 64 + mt * 16) * BSTR + k0) * 2 + a_off;
            uint32_t ah[4];
            ldm_x4(ah, ahp);
#pragma unroll
            for (int nt = 0; nt < 4; nt++)
                mma_bf16(acc[mt][nt], ah, bf[nt][0], bf[nt][1]);
        }
    }

    // ---- epilogue 2: P bf16 / Q fp32 ----
#pragma unroll
    for (int nt = 0; nt < 4; nt++) {
        int col = wc * 32 + nt * 8 + (lane & 3) * 2;
        float bias0 = 0.f, bias1 = 0.f;
        if (col >= 64) {
            bias0 = __ldg(b2 + col - 64);
            bias1 = __ldg(b2 + col - 63);
        }
#pragma unroll
        for (int mt = 0; mt < 4; mt++) {
            int row0 = mbase + wr * 64 + mt * 16 + (lane >> 2);
#pragma unroll
            for (int hrow = 0; hrow < 2; hrow++) {
                int row = row0 + hrow * 8;
                if (row < NN) {
                    float v0 = acc[mt][nt][hrow * 2];
                    float v1 = acc[mt][nt][hrow * 2 + 1];
                    if (col < 64) {
                        g_pbf[(size_t)row * 32 + (col >> 1)] = pack_bf16x2(v0, v1);
                    } else {
                        *(float2*)(g_q + (size_t)row * 64 + (col - 64)) =
                            make_float2(v0 + bias0, v1 + bias1);
                    }
                }
            }
        }
    }
}

// ======================= final: log_softmax(mean_agg(P) + Q), unroll 8 ==========
__global__ void k_final(float* __restrict__ out) {
    int node = blockIdx.x * (blockDim.x >> 5) + (threadIdx.x >> 5);
    if (node >= NN) return;
    int lane = threadIdx.x & 31;
    int b = g_rowptr[node], e = g_rowptr[node + 1];
    float a0 = 0.f, a1 = 0.f;
    int i = b;
    for (; i + 8 <= e; i += 8) {
        int u0 = g_col[i + 0], u1 = g_col[i + 1], u2 = g_col[i + 2], u3 = g_col[i + 3];
        int u4 = g_col[i + 4], u5 = g_col[i + 5], u6 = g_col[i + 6], u7 = g_col[i + 7];
        uint32_t w0 = g_pbf[(size_t)u0 * 32 + lane];
        uint32_t w1 = g_pbf[(size_t)u1 * 32 + lane];
        uint32_t w2 = g_pbf[(size_t)u2 * 32 + lane];
        uint32_t w3 = g_pbf[(size_t)u3 * 32 + lane];
        uint32_t w4 = g_pbf[(size_t)u4 * 32 + lane];
        uint32_t w5 = g_pbf[(size_t)u5 * 32 + lane];
        uint32_t w6 = g_pbf[(size_t)u6 * 32 + lane];
        uint32_t w7 = g_pbf[(size_t)u7 * 32 + lane];
        a0 += ((bf_lo(w0) + bf_lo(w1)) + (bf_lo(w2) + bf_lo(w3)))
            + ((bf_lo(w4) + bf_lo(w5)) + (bf_lo(w6) + bf_lo(w7)));
        a1 += ((bf_hi(w0) + bf_hi(w1)) + (bf_hi(w2) + bf_hi(w3)))
            + ((bf_hi(w4) + bf_hi(w5)) + (bf_hi(w6) + bf_hi(w7)));
    }
    for (; i < e; i++) {
        uint32_t w = g_pbf[(size_t)g_col[i] * 32 + lane];
        a0 += bf_lo(w);
        a1 += bf_hi(w);
    }
    float inv = 1.f / (float)max(e - b, 1);
    float2 q = *((const float2*)(g_q + (size_t)node * 64) + lane);
    float r0 = a0 * inv + q.x;
    float r1 = a1 * inv + q.y;

    float mx = fmaxf(r0, r1);
#pragma unroll
    for (int off = 16; off > 0; off >>= 1)
        mx = fmaxf(mx, __shfl_xor_sync(0xffffffffu, mx, off));
    float se = expf(r0 - mx) + expf(r1 - mx);
#pragma unroll
    for (int off = 16; off > 0; off >>= 1)
        se += __shfl_xor_sync(0xffffffffu, se, off);
    float l = logf(se);
    float2 o = make_float2(r0 - mx - l, r1 - mx - l);
    *((float2*)(out + (size_t)node * CC) + lane) = o;
}

// ======================= launch =======================
extern "C" void kernel_launch(void* const* d_in, const int* in_sizes, int n_in,
                              void* d_out, int out_size) {
    const float* x   = (const float*)d_in[0];
    const int*   ei  = (const int*)d_in[1];
    const int*   src = ei;
    const int*   dst = ei + NE;
    const float* W1l = (const float*)d_in[2];
    const float* b1l = (const float*)d_in[3];
    const float* W1r = (const float*)d_in[4];
    const float* W2l = (const float*)d_in[5];
    const float* b2l = (const float*)d_in[6];
    const float* W2r = (const float*)d_in[7];
    float* out = (float*)d_out;

    const int SMEM0  = 2 * 128 * BSTR * 2;   // 69632
    const int SMEM12 = 3 * 128 * BSTR * 2;   // 104448
    static cudaStream_t s2 = nullptr;
    static cudaEvent_t evF = nullptr, evJ = nullptr;
    if (!s2) {
        cudaStreamCreateWithFlags(&s2, cudaStreamNonBlocking);
        cudaEventCreateWithFlags(&evF, cudaEventDisableTiming);
        cudaEventCreateWithFlags(&evJ, cudaEventDisableTiming);
        cudaFuncSetAttribute(k_gemm0,  cudaFuncAttributeMaxDynamicSharedMemorySize, SMEM0);
        cudaFuncSetAttribute(k_gemm12, cudaFuncAttributeMaxDynamicSharedMemorySize, SMEM12);
    }

    const int NB = (NN + 127) / 128;

    // ---- fork: side stream: prepW -> gemm0 (emits xbf + xrbf) ----
    cudaEventRecord(evF, 0);
    cudaStreamWaitEvent(s2, evF, 0);
    k_prepW<<<(128 * 256 + 128 * 128 + 255) / 256, 256, 0, s2>>>(W1l, W1r, W2l, W2r);
    k_gemm0<<<NB, 256, SMEM0, s2>>>(x);
    cudaEventRecord(evJ, s2);

    // ---- main chain: fused count+scan (grid barriers), then fill ----
    k_countscan<<<SCAN_NB, SCAN_B>>>(dst);
    k_fill<<<(NE / 4 + 255) / 256, 256>>>(src, dst);

    // ---- aggregation (needs g_xbf from gemm0), fused GEMM, final ----
    cudaStreamWaitEvent(0, evJ, 0);
    k_agg128<<<(NN + 7) / 8, 256>>>();
    k_gemm12<<<NB, 256, SMEM12>>>(b1l, b2l);
    k_final<<<(NN + 7) / 8, 256>>>(out);
}

// round 16
// speedup vs baseline: 1.0729x; 1.0729x over previous
#include <cuda_runtime.h>
#include <cuda_bf16.h>
#include <cstdint>

#define NN 100000
#define NE 1600000
#define FF 128
#define CC 64
#define SCAN_B 1024
#define SCAN_NB ((NN + SCAN_B - 1) / SCAN_B)   // 98
#define C0N 50048                               // agg chunk split (dst ranges)

// ======================= scratch (static device globals) =======================
__device__ int   g_cnt[NN];
__device__ int   g_rowptr[NN + 1];
__device__ int   g_cursor[NN];
__device__ unsigned long long g_stat[SCAN_NB];   // decoupled-lookback status
__device__ int   g_col[NE];
__device__ uint32_t g_xbf[(size_t)NN * 64];    // x packed bf16x2 (written by k_gemm0)
__device__ uint32_t g_m[(size_t)NN * 64];      // mean(x) packed bf16x2
__device__ uint32_t g_xrbf[(size_t)NN * 64];   // xr = x @ W1r^T packed bf16x2
__device__ uint32_t g_pbf[(size_t)NN * 32];    // P = h@W2l^T packed bf16x2
__device__ float g_q[(size_t)NN * 64];         // Q = h@W2r^T + b2l (fp32)
// weights as plain bf16, row-major [n][k]
__device__ unsigned short g_w1[128 * 256];     // [W1l | W1r]
__device__ unsigned short g_w2[128 * 128];     // [W2l ; W2r]

// ======================= small helpers =======================
__device__ __forceinline__ uint32_t smem_to_u32(const void* p) {
    uint32_t a;
    asm("{ .reg .u64 t; cvta.to.shared.u64 t, %1; cvt.u32.u64 %0, t; }" : "=r"(a) : "l"(p));
    return a;
}

__device__ __forceinline__ void ldm_x4(uint32_t* r, uint32_t addr) {
    asm volatile("ldmatrix.sync.aligned.m8n8.x4.shared.b16 {%0,%1,%2,%3}, [%4];"
                 : "=r"(r[0]), "=r"(r[1]), "=r"(r[2]), "=r"(r[3]) : "r"(addr));
}

__device__ __forceinline__ void mma_bf16(float* d, const uint32_t* a, uint32_t b0, uint32_t b1) {
    asm volatile(
        "mma.sync.aligned.m16n8k16.row.col.f32.bf16.bf16.f32 "
        "{%0,%1,%2,%3}, {%4,%5,%6,%7}, {%8,%9}, {%0,%1,%2,%3};"
        : "+f"(d[0]), "+f"(d[1]), "+f"(d[2]), "+f"(d[3])
        : "r"(a[0]), "r"(a[1]), "r"(a[2]), "r"(a[3]), "r"(b0), "r"(b1));
}

__device__ __forceinline__ uint32_t pack_bf16x2(float a, float b) {
    return (uint32_t)__bfloat16_as_ushort(__float2bfloat16(a))
         | ((uint32_t)__bfloat16_as_ushort(__float2bfloat16(b)) << 16);
}

__device__ __forceinline__ float bf_lo(uint32_t w) { return __uint_as_float(w << 16); }
__device__ __forceinline__ float bf_hi(uint32_t w) { return __uint_as_float(w & 0xffff0000u); }

// ======================= CSR build =======================
// count: 4 edges per thread (int4); also resets the scan status array
__global__ void k_count(const int* __restrict__ dst) {
    int t = blockIdx.x * blockDim.x + threadIdx.x;
    if (t < SCAN_NB) g_stat[t] = 0ULL;
    int e = t * 4;
    if (e < NE) {
        int4 d = *(const int4*)(dst + e);
        atomicAdd(&g_cnt[d.x], 1);
        atomicAdd(&g_cnt[d.y], 1);
        atomicAdd(&g_cnt[d.z], 1);
        atomicAdd(&g_cnt[d.w], 1);
    }
}

// single-pass exclusive scan with WARP-PARALLEL decoupled lookback.
__global__ void __launch_bounds__(SCAN_B)
k_scan() {
    __shared__ int warp_sums[32];
    __shared__ int s_base;
    const int t = threadIdx.x, lane = t & 31, wid = t >> 5;
    const int tile = blockIdx.x;
    const int i = tile * SCAN_B + t;
    int v = (i < NN) ? g_cnt[i] : 0;
    if (i < NN) g_cnt[i] = 0;     // re-zero for next replay

    int s = v;
#pragma unroll
    for (int o = 1; o < 32; o <<= 1) {
        int u = __shfl_up_sync(0xffffffffu, s, o);
        if (lane >= o) s += u;
    }
    if (lane == 31) warp_sums[wid] = s;
    __syncthreads();
    if (wid == 0) {
        int ws = warp_sums[lane];
#pragma unroll
        for (int o = 1; o < 32; o <<= 1) {
            int u = __shfl_up_sync(0xffffffffu, ws, o);
            if (lane >= o) ws += u;
        }
        warp_sums[lane] = ws;
    }
    __syncthreads();
    const int incl  = s + (wid ? warp_sums[wid - 1] : 0);
    const int total = warp_sums[31];

    if (wid == 0) {
        if (tile == 0) {
            if (lane == 0) {
                __threadfence();
                atomicExch(&g_stat[0], (2ULL << 32) | (unsigned)total);
                s_base = 0;
            }
        } else {
            if (lane == 0) {
                __threadfence();
                atomicExch(&g_stat[tile], (1ULL << 32) | (unsigned)total);
            }
            __syncwarp();
            int exc = 0;
            int wend = tile;
            bool done = false;
            while (!done) {
                int j = wend - 32 + lane;
                unsigned long long st = (j >= 0) ? atomicAdd(&g_stat[j], 0ULL)
                                                 : (2ULL << 32);
                unsigned flag = (unsigned)(st >> 32);
                if (__all_sync(0xffffffffu, flag != 0u)) {
                    unsigned f2 = __ballot_sync(0xffffffffu, flag == 2u);
                    int val = (int)(unsigned)st;
                    if (f2) {
                        int hi = 31 - __clz(f2);
                        int add = (lane >= hi) ? val : 0;
#pragma unroll
                        for (int o = 16; o; o >>= 1) add += __shfl_xor_sync(0xffffffffu, add, o);
                        exc += add;
                        done = true;
                    } else {
                        int add = val;
#pragma unroll
                        for (int o = 16; o; o >>= 1) add += __shfl_xor_sync(0xffffffffu, add, o);
                        exc += add;
                        wend -= 32;
                    }
                }
            }
            if (lane == 0) {
                __threadfence();
                atomicExch(&g_stat[tile], (2ULL << 32) | (unsigned)(exc + total));
                s_base = exc;
            }
        }
    }
    __syncthreads();
    if (i < NN) {
        int r = s_base + incl - v;
        g_rowptr[i] = r;
        g_cursor[i] = r;
    }
    if (i == 0) g_rowptr[NN] = NE;
}

// fill (dst-range partitioned): places only edges with dst in [lo, hi)
__global__ void k_fillr(const int* __restrict__ src, const int* __restrict__ dst,
                        int lo, int hi) {
    int e = (blockIdx.x * blockDim.x + threadIdx.x) * 4;
    if (e < NE) {
        int4 d = *(const int4*)(dst + e);
        int4 s = *(const int4*)(src + e);
        if (d.x >= lo && d.x < hi) { int p = atomicAdd(&g_cursor[d.x], 1); g_col[p] = s.x; }
        if (d.y >= lo && d.y < hi) { int p = atomicAdd(&g_cursor[d.y], 1); g_col[p] = s.y; }
        if (d.z >= lo && d.z < hi) { int p = atomicAdd(&g_cursor[d.z], 1); g_col[p] = s.z; }
        if (d.w >= lo && d.w < hi) { int p = atomicAdd(&g_cursor[d.w], 1); g_col[p] = s.w; }
    }
}

// ======================= aggregation (warp per node, bf16 gather, unroll 8) =======
__global__ void k_agg128(int nodeBase, int nodeCount) {
    int n = blockIdx.x * (blockDim.x >> 5) + (threadIdx.x >> 5);
    if (n >= nodeCount) return;
    int node = nodeBase + n;
    int lane = threadIdx.x & 31;
    int b = g_rowptr[node], e = g_rowptr[node + 1];
    float a0 = 0.f, a1 = 0.f, a2 = 0.f, a3 = 0.f;
    int i = b;
    for (; i + 8 <= e; i += 8) {
        int u0 = g_col[i + 0], u1 = g_col[i + 1], u2 = g_col[i + 2], u3 = g_col[i + 3];
        int u4 = g_col[i + 4], u5 = g_col[i + 5], u6 = g_col[i + 6], u7 = g_col[i + 7];
        uint2 w0 = *((const uint2*)(g_xbf + (size_t)u0 * 64) + lane);
        uint2 w1 = *((const uint2*)(g_xbf + (size_t)u1 * 64) + lane);
        uint2 w2 = *((const uint2*)(g_xbf + (size_t)u2 * 64) + lane);
        uint2 w3 = *((const uint2*)(g_xbf + (size_t)u3 * 64) + lane);
        uint2 w4 = *((const uint2*)(g_xbf + (size_t)u4 * 64) + lane);
        uint2 w5 = *((const uint2*)(g_xbf + (size_t)u5 * 64) + lane);
        uint2 w6 = *((const uint2*)(g_xbf + (size_t)u6 * 64) + lane);
        uint2 w7 = *((const uint2*)(g_xbf + (size_t)u7 * 64) + lane);
        a0 += ((bf_lo(w0.x) + bf_lo(w1.x)) + (bf_lo(w2.x) + bf_lo(w3.x)))
            + ((bf_lo(w4.x) + bf_lo(w5.x)) + (bf_lo(w6.x) + bf_lo(w7.x)));
        a1 += ((bf_hi(w0.x) + bf_hi(w1.x)) + (bf_hi(w2.x) + bf_hi(w3.x)))
            + ((bf_hi(w4.x) + bf_hi(w5.x)) + (bf_hi(w6.x) + bf_hi(w7.x)));
        a2 += ((bf_lo(w0.y) + bf_lo(w1.y)) + (bf_lo(w2.y) + bf_lo(w3.y)))
            + ((bf_lo(w4.y) + bf_lo(w5.y)) + (bf_lo(w6.y) + bf_lo(w7.y)));
        a3 += ((bf_hi(w0.y) + bf_hi(w1.y)) + (bf_hi(w2.y) + bf_hi(w3.y)))
            + ((bf_hi(w4.y) + bf_hi(w5.y)) + (bf_hi(w6.y) + bf_hi(w7.y)));
    }
    for (; i < e; i++) {
        uint2 w = *((const uint2*)(g_xbf + (size_t)g_col[i] * 64) + lane);
        a0 += bf_lo(w.x); a1 += bf_hi(w.x);
        a2 += bf_lo(w.y); a3 += bf_hi(w.y);
    }
    float inv = 1.f / (float)max(e - b, 1);
    *((uint2*)(g_m + (size_t)node * 64) + lane) =
        make_uint2(pack_bf16x2(a0 * inv, a1 * inv), pack_bf16x2(a2 * inv, a3 * inv));
}

// ======================= weight prep (plain bf16) =======================
__global__ void k_prepW(const float* __restrict__ W1l, const float* __restrict__ W1r,
                        const float* __restrict__ W2l, const float* __restrict__ W2r) {
    int idx = blockIdx.x * blockDim.x + threadIdx.x;
    if (idx < 128 * 256) {
        int n = idx >> 8, k = idx & 255;
        float w = (k < 128) ? W1l[n * 128 + k] : W1r[n * 128 + (k - 128)];
        g_w1[idx] = __bfloat16_as_ushort(__float2bfloat16(w));
    } else {
        int i2 = idx - 128 * 256;
        if (i2 < 128 * 128) {
            int n = i2 >> 7, k = i2 & 127;
            float w = (n < 64) ? W2l[n * 128 + k] : W2r[(n - 64) * 128 + k];
            g_w2[i2] = __bfloat16_as_ushort(__float2bfloat16(w));
        }
    }
}

// ======================= single-term bf16 HMMA GEMMs =======================
#define BSTR 136   // bf16 per smem row (272B: conflict-free ldmatrix/frag access)

// GEMM 0 (side stream): xr = x @ W1r^T  -> g_xrbf ; ALSO emits g_xbf = bf16(x)
__global__ void __launch_bounds__(256, 2)
k_gemm0(const float* __restrict__ X)
{
    constexpr int AOFF = 0;
    constexpr int BOFF = 128 * BSTR * 2;   // 34816
    extern __shared__ char smem[];
    const uint32_t smem_base = smem_to_u32(smem);
    const int tid = threadIdx.x, warp = tid >> 5, lane = tid & 31;
    const int wr = warp >> 2, wc = warp & 3;
    const int mbase = blockIdx.x * 128;

    for (int i = tid; i < 128 * 16; i += 256) {
        int n = i >> 4, c = i & 15;
        *(uint4*)(smem + BOFF + n * (BSTR * 2) + c * 16) = ((const uint4*)g_w1)[n * 32 + 16 + c];
    }
    // A-load: read x fp32, convert once, feed smem AND g_xbf
    {
        int row = tid >> 1, half = tid & 1;
        int gr = mbase + row;
        bool valid = gr < NN;
        const float4* srcf = (const float4*)(X + (size_t)gr * 128 + half * 64);
        uint32_t* dA = (uint32_t*)(smem + AOFF + row * (BSTR * 2) + half * 128);
        uint32_t* dG = g_xbf + (size_t)gr * 64 + half * 32;
        uint32_t pk[32];
#pragma unroll
        for (int j = 0; j < 16; j++) {
            float4 v = make_float4(0.f, 0.f, 0.f, 0.f);
            if (valid) v = srcf[j];
            pk[2 * j]     = pack_bf16x2(v.x, v.y);
            pk[2 * j + 1] = pack_bf16x2(v.z, v.w);
        }
#pragma unroll
        for (int j = 0; j < 8; j++)
            *(uint4*)(dA + j * 4) = make_uint4(pk[4 * j], pk[4 * j + 1], pk[4 * j + 2], pk[4 * j + 3]);
        if (valid) {
#pragma unroll
            for (int j = 0; j < 8; j++)
                *(uint4*)(dG + j * 4) = make_uint4(pk[4 * j], pk[4 * j + 1], pk[4 * j + 2], pk[4 * j + 3]);
        }
    }
    __syncthreads();

    float acc[4][4][4];
#pragma unroll
    for (int mt = 0; mt < 4; mt++)
#pragma unroll
        for (int nt = 0; nt < 4; nt++)
#pragma unroll
            for (int q = 0; q < 4; q++) acc[mt][nt][q] = 0.f;

    const uint32_t a_off = (uint32_t)(((lane & 15) * BSTR + (lane >> 4) * 8) * 2);
    const uint32_t* Bp = (const uint32_t*)(smem + BOFF);

#pragma unroll
    for (int ks = 0; ks < 8; ks++) {
        const int k0 = ks * 16;
        uint32_t bf[4][2];
#pragma unroll
        for (int nt = 0; nt < 4; nt++) {
            int n = wc * 32 + nt * 8 + (lane >> 2);
            int bi = n * (BSTR / 2) + k0 / 2 + (lane & 3);
            bf[nt][0] = Bp[bi]; bf[nt][1] = Bp[bi + 4];
        }
#pragma unroll
        for (int mt = 0; mt < 4; mt++) {
            uint32_t ahp = smem_base + AOFF + (uint32_t)((wr * 64 + mt * 16) * BSTR + k0) * 2 + a_off;
            uint32_t ah[4];
            ldm_x4(ah, ahp);
#pragma unroll
            for (int nt = 0; nt < 4; nt++)
                mma_bf16(acc[mt][nt], ah, bf[nt][0], bf[nt][1]);
        }
    }

#pragma unroll
    for (int nt = 0; nt < 4; nt++) {
        int col = wc * 32 + nt * 8 + (lane & 3) * 2;
#pragma unroll
        for (int mt = 0; mt < 4; mt++) {
            int row0 = mbase + wr * 64 + mt * 16 + (lane >> 2);
#pragma unroll
            for (int hrow = 0; hrow < 2; hrow++) {
                int row = row0 + hrow * 8;
                if (row < NN)
                    g_xrbf[(size_t)row * 64 + (col >> 1)] =
                        pack_bf16x2(acc[mt][nt][hrow * 2], acc[mt][nt][hrow * 2 + 1]);
            }
        }
    }
}

// fused GEMM 1+2 (A = g_m from global)
__global__ void __launch_bounds__(256, 2)
k_gemm12(const float* __restrict__ b1, const float* __restrict__ b2)
{
    constexpr int AOFF = 0;
    constexpr int BOFF = 128 * BSTR * 2;       // 34816
    constexpr int HOFF = 2 * 128 * BSTR * 2;   // 69632 ; total 104448
    extern __shared__ char smem[];
    const uint32_t smem_base = smem_to_u32(smem);
    const int tid = threadIdx.x, warp = tid >> 5, lane = tid & 31;
    const int wr = warp >> 2, wc = warp & 3;
    const int mbase = blockIdx.x * 128;

    for (int i = tid; i < 128 * 16; i += 256) {
        int n = i >> 4, c = i & 15;
        *(uint4*)(smem + BOFF + n * (BSTR * 2) + c * 16) = ((const uint4*)g_w1)[n * 32 + c];
    }
    {
        int row = tid >> 1, half = tid & 1;
        int gr = mbase + row;
        bool valid = gr < NN;
        const uint4* src = (const uint4*)(g_m + (size_t)gr * 64 + half * 32);
        char* dA = smem + AOFF + row * (BSTR * 2) + half * 128;
#pragma unroll
        for (int j = 0; j < 8; j++) {
            uint4 v = make_uint4(0u, 0u, 0u, 0u);
            if (valid) v = src[j];
            *(uint4*)(dA + j * 16) = v;
        }
    }
    __syncthreads();

    float acc[4][4][4];
#pragma unroll
    for (int mt = 0; mt < 4; mt++)
#pragma unroll
        for (int nt = 0; nt < 4; nt++)
#pragma unroll
            for (int q = 0; q < 4; q++) acc[mt][nt][q] = 0.f;

    const uint32_t a_off = (uint32_t)(((lane & 15) * BSTR + (lane >> 4) * 8) * 2);
    const uint32_t* Bp = (const uint32_t*)(smem + BOFF);

    // ---- mainloop 1 ----
#pragma unroll
    for (int ks = 0; ks < 8; ks++) {
        const int k0 = ks * 16;
        uint32_t bf[4][2];
#pragma unroll
        for (int nt = 0; nt < 4; nt++) {
            int n = wc * 32 + nt * 8 + (lane >> 2);
            int bi = n * (BSTR / 2) + k0 / 2 + (lane & 3);
            bf[nt][0] = Bp[bi]; bf[nt][1] = Bp[bi + 4];
        }
#pragma unroll
        for (int mt = 0; mt < 4; mt++) {
            uint32_t ahp = smem_base + AOFF + (uint32_t)((wr * 64 + mt * 16) * BSTR + k0) * 2 + a_off;
            uint32_t ah[4];
            ldm_x4(ah, ahp);
#pragma unroll
            for (int nt = 0; nt < 4; nt++)
                mma_bf16(acc[mt][nt], ah, bf[nt][0], bf[nt][1]);
        }
    }

    // ---- epilogue 1: h -> smem H (bf16) ----
#pragma unroll
    for (int nt = 0; nt < 4; nt++) {
        int col = wc * 32 + nt * 8 + (lane & 3) * 2;
        float bias0 = __ldg(b1 + col);
        float bias1 = __ldg(b1 + col + 1);
#pragma unroll
        for (int mt = 0; mt < 4; mt++) {
            int rl0 = wr * 64 + mt * 16 + (lane >> 2);
#pragma unroll
            for (int hrow = 0; hrow < 2; hrow++) {
                int rl = rl0 + hrow * 8;
                int grow = mbase + rl;
                float xr0 = 0.f, xr1 = 0.f;
                if (grow < NN) {
                    uint32_t w = g_xrbf[(size_t)grow * 64 + (col >> 1)];
                    xr0 = bf_lo(w); xr1 = bf_hi(w);
                }
                float v0 = fmaxf(acc[mt][nt][hrow * 2]     + xr0 + bias0, 0.f);
                float v1 = fmaxf(acc[mt][nt][hrow * 2 + 1] + xr1 + bias1, 0.f);
                *(uint32_t*)(smem + HOFF + rl * (BSTR * 2) + (col >> 1) * 4) = pack_bf16x2(v0, v1);
            }
        }
    }
    __syncthreads();

    // ---- W2 into B region ----
    for (int i = tid; i < 128 * 16; i += 256) {
        int n = i >> 4, c = i & 15;
        *(uint4*)(smem + BOFF + n * (BSTR * 2) + c * 16) = ((const uint4*)g_w2)[n * 16 + c];
    }
#pragma unroll
    for (int mt = 0; mt < 4; mt++)
#pragma unroll
        for (int nt = 0; nt < 4; nt++)
#pragma unroll
            for (int q = 0; q < 4; q++) acc[mt][nt][q] = 0.f;
    __syncthreads();

    // ---- mainloop 2: A = H ----
#pragma unroll
    for (int ks = 0; ks < 8; ks++) {
        const int k0 = ks * 16;
        uint32_t bf[4][2];
#pragma unroll
        for (int nt = 0; nt < 4; nt++) {
            int n = wc * 32 + nt * 8 + (lane >> 2);
            int bi = n * (BSTR / 2) + k0 / 2 + (lane & 3);
            bf[nt][0] = Bp[bi]; bf[nt][1] = Bp[bi + 4];
        }
#pragma unroll
        for (int mt = 0; mt < 4; mt++) {
            uint32_t ahp = smem_base + HOFF + (uint32_t)((wr * 64 + mt * 16) * BSTR + k0) * 2 + a_off;
            uint32_t ah[4];
            ldm_x4(ah, ahp);
#pragma unroll
            for (int nt = 0; nt < 4; nt++)
                mma_bf16(acc[mt][nt], ah, bf[nt][0], bf[nt][1]);
        }
    }

    // ---- epilogue 2: P bf16 / Q fp32 ----
#pragma unroll
    for (int nt = 0; nt < 4; nt++) {
        int col = wc * 32 + nt * 8 + (lane & 3) * 2;
        float bias0 = 0.f, bias1 = 0.f;
        if (col >= 64) {
            bias0 = __ldg(b2 + col - 64);
            bias1 = __ldg(b2 + col - 63);
        }
#pragma unroll
        for (int mt = 0; mt < 4; mt++) {
            int row0 = mbase + wr * 64 + mt * 16 + (lane >> 2);
#pragma unroll
            for (int hrow = 0; hrow < 2; hrow++) {
                int row = row0 + hrow * 8;
                if (row < NN) {
                    float v0 = acc[mt][nt][hrow * 2];
                    float v1 = acc[mt][nt][hrow * 2 + 1];
                    if (col < 64) {
                        g_pbf[(size_t)row * 32 + (col >> 1)] = pack_bf16x2(v0, v1);
                    } else {
                        *(float2*)(g_q + (size_t)row * 64 + (col - 64)) =
                            make_float2(v0 + bias0, v1 + bias1);
                    }
                }
            }
        }
    }
}

// ======================= final: log_softmax(mean_agg(P) + Q), unroll 8 ==========
__global__ void k_final(float* __restrict__ out) {
    int node = blockIdx.x * (blockDim.x >> 5) + (threadIdx.x >> 5);
    if (node >= NN) return;
    int lane = threadIdx.x & 31;
    int b = g_rowptr[node], e = g_rowptr[node + 1];
    float a0 = 0.f, a1 = 0.f;
    int i = b;
    for (; i + 8 <= e; i += 8) {
        int u0 = g_col[i + 0], u1 = g_col[i + 1], u2 = g_col[i + 2], u3 = g_col[i + 3];
        int u4 = g_col[i + 4], u5 = g_col[i + 5], u6 = g_col[i + 6], u7 = g_col[i + 7];
        uint32_t w0 = g_pbf[(size_t)u0 * 32 + lane];
        uint32_t w1 = g_pbf[(size_t)u1 * 32 + lane];
        uint32_t w2 = g_pbf[(size_t)u2 * 32 + lane];
        uint32_t w3 = g_pbf[(size_t)u3 * 32 + lane];
        uint32_t w4 = g_pbf[(size_t)u4 * 32 + lane];
        uint32_t w5 = g_pbf[(size_t)u5 * 32 + lane];
        uint32_t w6 = g_pbf[(size_t)u6 * 32 + lane];
        uint32_t w7 = g_pbf[(size_t)u7 * 32 + lane];
        a0 += ((bf_lo(w0) + bf_lo(w1)) + (bf_lo(w2) + bf_lo(w3)))
            + ((bf_lo(w4) + bf_lo(w5)) + (bf_lo(w6) + bf_lo(w7)));
        a1 += ((bf_hi(w0) + bf_hi(w1)) + (bf_hi(w2) + bf_hi(w3)))
            + ((bf_hi(w4) + bf_hi(w5)) + (bf_hi(w6) + bf_hi(w7)));
    }
    for (; i < e; i++) {
        uint32_t w = g_pbf[(size_t)g_col[i] * 32 + lane];
        a0 += bf_lo(w);
        a1 += bf_hi(w);
    }
    float inv = 1.f / (float)max(e - b, 1);
    float2 q = *((const float2*)(g_q + (size_t)node * 64) + lane);
    float r0 = a0 * inv + q.x;
    float r1 = a1 * inv + q.y;

    float mx = fmaxf(r0, r1);
#pragma unroll
    for (int off = 16; off > 0; off >>= 1)
        mx = fmaxf(mx, __shfl_xor_sync(0xffffffffu, mx, off));
    float se = expf(r0 - mx) + expf(r1 - mx);
#pragma unroll
    for (int off = 16; off > 0; off >>= 1)
        se += __shfl_xor_sync(0xffffffffu, se, off);
    float l = logf(se);
    float2 o = make_float2(r0 - mx - l, r1 - mx - l);
    *((float2*)(out + (size_t)node * CC) + lane) = o;
}

// ======================= launch =======================
extern "C" void kernel_launch(void* const* d_in, const int* in_sizes, int n_in,
                              void* d_out, int out_size) {
    const float* x   = (const float*)d_in[0];
    const int*   ei  = (const int*)d_in[1];
    const int*   src = ei;
    const int*   dst = ei + NE;
    const float* W1l = (const float*)d_in[2];
    const float* b1l = (const float*)d_in[3];
    const float* W1r = (const float*)d_in[4];
    const float* W2l = (const float*)d_in[5];
    const float* b2l = (const float*)d_in[6];
    const float* W2r = (const float*)d_in[7];
    float* out = (float*)d_out;

    const int SMEM0  = 2 * 128 * BSTR * 2;   // 69632
    const int SMEM12 = 3 * 128 * BSTR * 2;   // 104448
    static cudaStream_t s2 = nullptr, s3 = nullptr;
    static cudaEvent_t evF = nullptr, evJ = nullptr, evFA = nullptr, evA0 = nullptr;
    if (!s2) {
        cudaStreamCreateWithFlags(&s2, cudaStreamNonBlocking);
        cudaStreamCreateWithFlags(&s3, cudaStreamNonBlocking);
        cudaEventCreateWithFlags(&evF, cudaEventDisableTiming);
        cudaEventCreateWithFlags(&evJ, cudaEventDisableTiming);
        cudaEventCreateWithFlags(&evFA, cudaEventDisableTiming);
        cudaEventCreateWithFlags(&evA0, cudaEventDisableTiming);
        cudaFuncSetAttribute(k_gemm0,  cudaFuncAttributeMaxDynamicSharedMemorySize, SMEM0);
        cudaFuncSetAttribute(k_gemm12, cudaFuncAttributeMaxDynamicSharedMemorySize, SMEM12);
    }

    const int NB = (NN + 127) / 128;
    const int FB = (NE / 4 + 255) / 256;

    // ---- fork: side stream: prepW -> gemm0 (emits xbf + xrbf) ----
    cudaEventRecord(evF, 0);
    cudaStreamWaitEvent(s2, evF, 0);
    k_prepW<<<(128 * 256 + 128 * 128 + 255) / 256, 256, 0, s2>>>(W1l, W1r, W2l, W2r);
    k_gemm0<<<NB, 256, SMEM0, s2>>>(x);
    cudaEventRecord(evJ, s2);

    // ---- main chain: count -> scan -> fill_a (dst < C0N) ----
    k_count<<<FB, 256>>>(dst);
    k_scan<<<SCAN_NB, SCAN_B>>>();
    k_fillr<<<FB, 256>>>(src, dst, 0, C0N);
    cudaEventRecord(evFA, 0);

    // ---- s3: agg chunk 0 overlaps fill_b (needs g_xbf + chunk-0 CSR) ----
    cudaStreamWaitEvent(s3, evFA, 0);
    cudaStreamWaitEvent(s3, evJ, 0);
    k_agg128<<<(C0N + 7) / 8, 256, 0, s3>>>(0, C0N);
    cudaEventRecord(evA0, s3);

    // ---- main: fill_b (dst >= C0N), agg chunk 1 ----
    k_fillr<<<FB, 256>>>(src, dst, C0N, NN);
    cudaStreamWaitEvent(0, evJ, 0);
    k_agg128<<<((NN - C0N) + 7) / 8, 256>>>(C0N, NN - C0N);

    // ---- join chunk 0, fused GEMM, final ----
    cudaStreamWaitEvent(0, evA0, 0);
    k_gemm12<<<NB, 256, SMEM12>>>(b1l, b2l);
    k_final<<<(NN + 7) / 8, 256>>>(out);
}